// round 17
// baseline (speedup 1.0000x reference)
#include <cuda_runtime.h>
#include <cuda_bf16.h>
#include <math.h>
#include <stdint.h>

#define Lseq 2048
#define Dm   1024
#define Hh   16
#define HD   64
#define Pp   128
#define PPH  8
#define DA   80
#define KQ3  240       // 3*80 packed augmented dim for attention S
#define K2   2048      // [hi|lo] packed K for projection GEMMs
#define CONTENT_SCALE 0.125f
#define PHASE_SCALE   0.35355339059327373f
#define NEG_BIG (-1e30f)

// ---------------- scratch (static device globals) ----------------
__device__ float g_QtKt[Lseq*2*Pp];
__device__ float g_P2[Lseq*Dm];
__device__ float g_invf[64];
__device__ __nv_bfloat16 g_Ab  [Lseq*K2];
__device__ __nv_bfloat16 g_Aib [Lseq*K2];
__device__ __nv_bfloat16 g_AOb [Lseq*K2];
__device__ __nv_bfloat16 g_Bqkv[3*Dm*K2];
__device__ __nv_bfloat16 g_Bp2 [2*Pp*K2];
__device__ __nv_bfloat16 g_Bo  [Dm*K2];
__device__ __nv_bfloat16 g_Qb [Hh*Lseq*KQ3];
__device__ __nv_bfloat16 g_Kb [Hh*Lseq*KQ3];
__device__ __nv_bfloat16 g_Vth[Hh*HD*Lseq];
__device__ __nv_bfloat16 g_Vtl[Hh*HD*Lseq];

// ---------------- helpers ----------------
__device__ __forceinline__ uint32_t smem_u32(const void* p) {
    uint32_t a;
    asm("{ .reg .u64 t; cvta.to.shared.u64 t, %1; cvt.u32.u64 %0, t; }" : "=r"(a) : "l"(p));
    return a;
}
__device__ __forceinline__ void ldsm_x4(uint32_t& r0, uint32_t& r1, uint32_t& r2,
                                        uint32_t& r3, uint32_t addr) {
    asm volatile("ldmatrix.sync.aligned.m8n8.x4.shared.b16 {%0,%1,%2,%3}, [%4];"
                 : "=r"(r0), "=r"(r1), "=r"(r2), "=r"(r3) : "r"(addr));
}
__device__ __forceinline__ void mma_bf16(float* c, uint32_t a0, uint32_t a1,
                                         uint32_t a2, uint32_t a3,
                                         uint32_t b0, uint32_t b1) {
    asm volatile(
        "mma.sync.aligned.m16n8k16.row.col.f32.bf16.bf16.f32 "
        "{%0,%1,%2,%3}, {%4,%5,%6,%7}, {%8,%9}, {%0,%1,%2,%3};"
        : "+f"(c[0]), "+f"(c[1]), "+f"(c[2]), "+f"(c[3])
        : "r"(a0), "r"(a1), "r"(a2), "r"(a3), "r"(b0), "r"(b1));
}
__device__ __forceinline__ uint32_t pack_bf16x2(float a, float b) {
    __nv_bfloat162 h = __floats2bfloat162_rn(a, b);
    return *(uint32_t*)&h;
}
__device__ __forceinline__ void cp_async16(uint32_t dst, const void* src) {
    asm volatile("cp.async.cg.shared.global [%0], [%1], 16;" :: "r"(dst), "l"(src));
}
#define CP_COMMIT() asm volatile("cp.async.commit_group;" ::: "memory")
#define CP_WAIT0()  asm volatile("cp.async.wait_group 0;" ::: "memory")

// ---------------------------------------------------------------------------
// One-time inv_freq table init
// ---------------------------------------------------------------------------
__global__ void init_invf() {
    int f = threadIdx.x;
    if (f < 64)
        g_invf[f] = (float)exp(-(double)f / 64.0 * log(10000.0));
}

// ---------------------------------------------------------------------------
// Batched [hi|lo] pack of both activations
// ---------------------------------------------------------------------------
__global__ __launch_bounds__(256)
void conv_a2b(const float* __restrict__ X0, const float* __restrict__ X1,
              __nv_bfloat16* __restrict__ O0, __nv_bfloat16* __restrict__ O1) {
    const float* X = blockIdx.z ? X1 : X0;
    __nv_bfloat16* out = blockIdx.z ? O1 : O0;
    int idx = blockIdx.x * 256 + threadIdx.x;
    if (idx >= (Lseq * Dm) / 4) return;
    int m = idx >> 8, k4 = (idx & 255) * 4;
    float4 v = *(const float4*)(X + (size_t)m * 1024 + k4);
    uint32_t h0 = pack_bf16x2(v.x, v.y);
    uint32_t h1 = pack_bf16x2(v.z, v.w);
    __nv_bfloat162 a = *(__nv_bfloat162*)&h0;
    __nv_bfloat162 b = *(__nv_bfloat162*)&h1;
    uint32_t l0 = pack_bf16x2(v.x - __bfloat162float(a.x), v.y - __bfloat162float(a.y));
    uint32_t l1 = pack_bf16x2(v.z - __bfloat162float(b.x), v.w - __bfloat162float(b.y));
    size_t r = (size_t)m * K2;
    *(uint2*)&out[r + k4]        = make_uint2(h0, h1);
    *(uint2*)&out[r + 1024 + k4] = make_uint2(l0, l1);
}

// ---------------------------------------------------------------------------
// Batched [hi|lo] pack+transpose of all 6 weights
// ---------------------------------------------------------------------------
__global__ __launch_bounds__(256)
void conv_b2b(const float* __restrict__ Wq, const float* __restrict__ Wk,
              const float* __restrict__ Wv, const float* __restrict__ Wo,
              const float* __restrict__ Wqp, const float* __restrict__ Wkp,
              __nv_bfloat16* __restrict__ Bqkv, __nv_bfloat16* __restrict__ Bo,
              __nv_bfloat16* __restrict__ Bp2) {
    const int z = blockIdx.z;
    const float* W;
    __nv_bfloat16* out;
    int N;
    switch (z) {
        case 0: W = Wq;  out = Bqkv;                         N = Dm; break;
        case 1: W = Wk;  out = Bqkv + (size_t)Dm * K2;       N = Dm; break;
        case 2: W = Wv;  out = Bqkv + (size_t)2 * Dm * K2;   N = Dm; break;
        case 3: W = Wo;  out = Bo;                           N = Dm; break;
        case 4: W = Wqp; out = Bp2;                          N = Pp; break;
        default: W = Wkp; out = Bp2 + (size_t)Pp * K2;       N = Pp; break;
    }
    int n0 = blockIdx.x * 32;
    if (n0 >= N) return;
    __shared__ float t[32][33];
    int k0 = blockIdx.y * 32;
    int tx = threadIdx.x & 31, ty = threadIdx.x >> 5;
#pragma unroll
    for (int i = 0; i < 32; i += 8)
        t[ty + i][tx] = W[(size_t)(k0 + ty + i) * N + n0 + tx];
    __syncthreads();
#pragma unroll
    for (int i = 0; i < 32; i += 8) {
        float v = t[tx][ty + i];
        __nv_bfloat16 hi = __float2bfloat16(v);
        __nv_bfloat16 lo = __float2bfloat16(v - __bfloat162float(hi));
        size_t r = (size_t)(n0 + ty + i) * K2;
        out[r + k0 + tx] = hi;
        out[r + 1024 + k0 + tx] = lo;
    }
}

// ---------------------------------------------------------------------------
// Fused-epilogue store for the QKV GEMM
// ---------------------------------------------------------------------------
__device__ __forceinline__ void qkv_store(int row, int col, float v0, float v1,
        const float* __restrict__ alogit,
        __nv_bfloat16* __restrict__ Qb, __nv_bfloat16* __restrict__ Kb,
        __nv_bfloat16* __restrict__ Vth, __nv_bfloat16* __restrict__ Vtl) {
    if (col < 2048) {
        const bool isQ = (col < 1024);
        int c = col & 1023;
        int hh = c >> 6, d = c & 63;
        if (isQ) {
            float a = 1.f / (1.f + __expf(-alogit[hh]));
            float s = (1.f - a) * CONTENT_SCALE;
            v0 *= s; v1 *= s;
        }
        size_t base = ((size_t)hh * Lseq + row) * KQ3;
        uint32_t hi = pack_bf16x2(v0, v1);
        __nv_bfloat162 h2 = *(__nv_bfloat162*)&hi;
        uint32_t lo = pack_bf16x2(v0 - __bfloat162float(h2.x),
                                  v1 - __bfloat162float(h2.y));
        __nv_bfloat16* dst = isQ ? Qb : Kb;
        *(uint32_t*)&dst[base + d]       = hi;
        *(uint32_t*)&dst[base + 80 + d]  = isQ ? lo : hi;
        *(uint32_t*)&dst[base + 160 + d] = isQ ? hi : lo;
    } else {
        int c2 = col - 2048;
        __nv_bfloat16 h0 = __float2bfloat16(v0);
        __nv_bfloat16 h1 = __float2bfloat16(v1);
        Vth[(size_t)c2 * Lseq + row]       = h0;
        Vth[(size_t)(c2 + 1) * Lseq + row] = h1;
        Vtl[(size_t)c2 * Lseq + row]       = __float2bfloat16(v0 - __bfloat162float(h0));
        Vtl[(size_t)(c2 + 1) * Lseq + row] = __float2bfloat16(v1 - __bfloat162float(h1));
    }
}

#define LDA 40
#define TG3_TILE (128*LDA)
#define TG3_BUF  (4*TG3_TILE)
#define TG3_SMEM (2*TG3_BUF*2)   // 81920 bytes

// ---------------------------------------------------------------------------
// GEMM mainloop (3-pass split, cp.async pipelined).
// A-fragment registers are REUSED across the hi/lo passes (load ah -> 2 mma
// passes -> overwrite with al -> 1 mma pass) to keep live regs < 128 and
// avoid the spills the R16 profile showed (regs pinned at cap, L1 42%).
// ---------------------------------------------------------------------------
__device__ __forceinline__ void gemm_main(
        const __nv_bfloat16* __restrict__ A, const __nv_bfloat16* __restrict__ B,
        int m0, int n0, __nv_bfloat16* sm3, float acc[4][4][4],
        int tid, int wid, int lane, int wm, int wn) {
    const int lr = tid >> 1, lc = (tid & 1) * 16;
    const __nv_bfloat16* Agh = A + (size_t)(m0 + lr) * K2 + lc;
    const __nv_bfloat16* Agl = Agh + 1024;
    const __nv_bfloat16* Bgh = B + (size_t)(n0 + lr) * K2 + lc;
    const __nv_bfloat16* Bgl = Bgh + 1024;
    const uint32_t smB = smem_u32(sm3);
    const uint32_t so = (uint32_t)(lr * LDA + lc) * 2;

    auto ld_chunk = [&](int kt, int buf) {
        const uint32_t d = smB + (uint32_t)buf * TG3_BUF * 2;
        const int off = kt * 32;
        cp_async16(d + so,                      Agh + off);
        cp_async16(d + so + 16,                 Agh + off + 8);
        cp_async16(d + TG3_TILE*2 + so,         Agl + off);
        cp_async16(d + TG3_TILE*2 + so + 16,    Agl + off + 8);
        cp_async16(d + 2*TG3_TILE*2 + so,       Bgh + off);
        cp_async16(d + 2*TG3_TILE*2 + so + 16,  Bgh + off + 8);
        cp_async16(d + 3*TG3_TILE*2 + so,       Bgl + off);
        cp_async16(d + 3*TG3_TILE*2 + so + 16,  Bgl + off + 8);
    };

    ld_chunk(0, 0);
    CP_COMMIT();
    CP_WAIT0();
    __syncthreads();

    const int a_row = (lane & 15);
    const int a_koff = (lane >> 4) * 8;
    const int b_row = (lane & 7) + ((lane & 16) >> 1);
    const int b_koff = ((lane >> 3) & 1) * 8;

    for (int kt = 0; kt < 32; kt++) {
        const int cur = kt & 1;
        if (kt < 31) {
            ld_chunk(kt + 1, cur ^ 1);
            CP_COMMIT();
        }
        const uint32_t base = smB + (uint32_t)cur * TG3_BUF * 2;
        const uint32_t ahB = base;
        const uint32_t alB = base + TG3_TILE * 2;
        const uint32_t bhB = base + 2 * TG3_TILE * 2;
        const uint32_t blB = base + 3 * TG3_TILE * 2;
#pragma unroll
        for (int ks = 0; ks < 2; ks++) {
            const int k0 = ks * 16;
            uint32_t bh[2][4], bl[2][4];
#pragma unroll
            for (int nt2 = 0; nt2 < 2; nt2++) {
                ldsm_x4(bh[nt2][0], bh[nt2][1], bh[nt2][2], bh[nt2][3],
                        bhB + ((wn + nt2 * 16 + b_row) * LDA + k0 + b_koff) * 2);
                ldsm_x4(bl[nt2][0], bl[nt2][1], bl[nt2][2], bl[nt2][3],
                        blB + ((wn + nt2 * 16 + b_row) * LDA + k0 + b_koff) * 2);
            }
            // phase 1+2: A-hi fragments; ah*bh and ah*bl
            uint32_t af[4][4];
#pragma unroll
            for (int mt = 0; mt < 4; mt++)
                ldsm_x4(af[mt][0], af[mt][1], af[mt][2], af[mt][3],
                        ahB + ((wm + mt * 16 + a_row) * LDA + k0 + a_koff) * 2);
#pragma unroll
            for (int mt = 0; mt < 4; mt++)
#pragma unroll
                for (int nt = 0; nt < 4; nt++) {
                    mma_bf16(acc[mt][nt], af[mt][0], af[mt][1], af[mt][2], af[mt][3],
                             bh[nt >> 1][(nt & 1) * 2], bh[nt >> 1][(nt & 1) * 2 + 1]);
                    mma_bf16(acc[mt][nt], af[mt][0], af[mt][1], af[mt][2], af[mt][3],
                             bl[nt >> 1][(nt & 1) * 2], bl[nt >> 1][(nt & 1) * 2 + 1]);
                }
            // phase 3: overwrite with A-lo fragments; al*bh
#pragma unroll
            for (int mt = 0; mt < 4; mt++)
                ldsm_x4(af[mt][0], af[mt][1], af[mt][2], af[mt][3],
                        alB + ((wm + mt * 16 + a_row) * LDA + k0 + a_koff) * 2);
#pragma unroll
            for (int mt = 0; mt < 4; mt++)
#pragma unroll
                for (int nt = 0; nt < 4; nt++)
                    mma_bf16(acc[mt][nt], af[mt][0], af[mt][1], af[mt][2], af[mt][3],
                             bh[nt >> 1][(nt & 1) * 2], bh[nt >> 1][(nt & 1) * 2 + 1]);
        }
        if (kt < 31) {
            CP_WAIT0();
            __syncthreads();
        }
    }
}

// ---------------------------------------------------------------------------
// Fused QKV + phase GEMM: 1D grid.
// ---------------------------------------------------------------------------
__global__ __launch_bounds__(256, 2)
void tgemm_fused(const __nv_bfloat16* __restrict__ A1, const __nv_bfloat16* __restrict__ B1,
                 const __nv_bfloat16* __restrict__ A2, const __nv_bfloat16* __restrict__ B2,
                 float* __restrict__ C2,
                 const float* __restrict__ alogit,
                 __nv_bfloat16* __restrict__ Qb, __nv_bfloat16* __restrict__ Kb,
                 __nv_bfloat16* __restrict__ Vth, __nv_bfloat16* __restrict__ Vtl) {
    extern __shared__ __nv_bfloat16 sm3[];
    const int tid = threadIdx.x;
    const int wid = tid >> 5, lane = tid & 31;
    const int wm = (wid >> 2) * 64, wn = (wid & 3) * 32;
    const int bid = blockIdx.x;

    const bool qkv = (bid < 384);
    const __nv_bfloat16 *A, *B;
    int m0, n0;
    if (qkv) {
        A = A1; B = B1;
        m0 = (bid / 24) * 128; n0 = (bid % 24) * 128;
    } else {
        int p = bid - 384;
        A = A2; B = B2;
        m0 = (p >> 1) * 128; n0 = (p & 1) * 128;
    }

    float acc[4][4][4];
#pragma unroll
    for (int i = 0; i < 4; i++)
#pragma unroll
        for (int j = 0; j < 4; j++)
#pragma unroll
            for (int k = 0; k < 4; k++) acc[i][j][k] = 0.f;

    gemm_main(A, B, m0, n0, sm3, acc, tid, wid, lane, wm, wn);

    const int er = lane >> 2, ec = (lane & 3) * 2;
#pragma unroll
    for (int mt = 0; mt < 4; mt++) {
        const int row = m0 + wm + mt * 16 + er;
#pragma unroll
        for (int nt = 0; nt < 4; nt++) {
            const int col = n0 + wn + nt * 8 + ec;
            if (qkv) {
                qkv_store(row,     col, acc[mt][nt][0], acc[mt][nt][1],
                          alogit, Qb, Kb, Vth, Vtl);
                qkv_store(row + 8, col, acc[mt][nt][2], acc[mt][nt][3],
                          alogit, Qb, Kb, Vth, Vtl);
            } else {
                *(float2*)&C2[(size_t)row * 256 + col] =
                    make_float2(acc[mt][nt][0], acc[mt][nt][1]);
                *(float2*)&C2[(size_t)(row + 8) * 256 + col] =
                    make_float2(acc[mt][nt][2], acc[mt][nt][3]);
            }
        }
    }
}

// ---------------------------------------------------------------------------
// Plain GEMM (fp32 out) for the Wo projection.
// ---------------------------------------------------------------------------
__global__ __launch_bounds__(256, 2)
void tgemm3(const __nv_bfloat16* __restrict__ A, const __nv_bfloat16* __restrict__ B,
            float* __restrict__ C, int N) {
    extern __shared__ __nv_bfloat16 sm3[];
    const int tid = threadIdx.x;
    const int wid = tid >> 5, lane = tid & 31;
    const int m0 = blockIdx.y * 128, n0 = blockIdx.x * 128;
    const int wm = (wid >> 2) * 64, wn = (wid & 3) * 32;

    float acc[4][4][4];
#pragma unroll
    for (int i = 0; i < 4; i++)
#pragma unroll
        for (int j = 0; j < 4; j++)
#pragma unroll
            for (int k = 0; k < 4; k++) acc[i][j][k] = 0.f;

    gemm_main(A, B, m0, n0, sm3, acc, tid, wid, lane, wm, wn);

    const int er = lane >> 2, ec = (lane & 3) * 2;
#pragma unroll
    for (int mt = 0; mt < 4; mt++) {
        const int row = m0 + wm + mt * 16 + er;
#pragma unroll
        for (int nt = 0; nt < 4; nt++) {
            const int col = n0 + wn + nt * 8 + ec;
            *(float2*)&C[(size_t)row * N + col] =
                make_float2(acc[mt][nt][0], acc[mt][nt][1]);
            *(float2*)&C[(size_t)(row + 8) * N + col] =
                make_float2(acc[mt][nt][2], acc[mt][nt][3]);
        }
    }
}

// ---------------------------------------------------------------------------
// Phase dims (64..79) packed bf16x3; fp32 inv_freq table, no fp64 hot path.
// ---------------------------------------------------------------------------
__global__ __launch_bounds__(256)
void phase_pack(const float* __restrict__ QtKt,
                const float* __restrict__ bqp, const float* __restrict__ bkp,
                const float* __restrict__ alogit,
                __nv_bfloat16* __restrict__ Qb, __nv_bfloat16* __restrict__ Kb) {
    __shared__ float invf_s[64];
    const int tid = threadIdx.x;
    if (tid < 64) invf_s[tid] = g_invf[tid];
    __syncthreads();

    int idx = blockIdx.x * 256 + tid;
    if (idx >= Lseq * Pp) return;
    int q = idx >> 7, j = idx & 127;
    int h = j / PPH, i = j % PPH;
    int f = j >> 1;
    float pos = (float)q * invf_s[f];
    float tq = QtKt[(size_t)q * 256 + j] + bqp[j] + pos;
    float tk = QtKt[(size_t)q * 256 + 128 + j] + bkp[j] + pos;
    float alpha = 1.f / (1.f + expf(-alogit[h]));
    float aps = alpha * PHASE_SCALE;
    size_t base = ((size_t)h * Lseq + q) * KQ3;
    float cq, sq, ck, sk;
    sincosf(tq, &sq, &cq);
    sincosf(tk, &sk, &ck);
    float qv[2] = {aps * cq, aps * sq};
    float kv[2] = {ck, sk};
#pragma unroll
    for (int s = 0; s < 2; s++) {
        int d = 64 + s * 8 + i;
        __nv_bfloat16 qh = __float2bfloat16(qv[s]);
        __nv_bfloat16 ql = __float2bfloat16(qv[s] - __bfloat162float(qh));
        Qb[base + d] = qh; Qb[base + 80 + d] = ql; Qb[base + 160 + d] = qh;
        __nv_bfloat16 kh = __float2bfloat16(kv[s]);
        __nv_bfloat16 kl = __float2bfloat16(kv[s] - __bfloat162float(kh));
        Kb[base + d] = kh; Kb[base + 80 + d] = kh; Kb[base + 160 + d] = kl;
    }
}

// ---------------------------------------------------------------------------
// Tensor-core flash attention v4, 1D load-balanced grid.
// ---------------------------------------------------------------------------
#define QS_STR 248
#define KS_STR 248
#define VS_STR 72
#define A4B_VH (64*KS_STR*2)
#define A4B_VL (A4B_VH + 64*VS_STR*2)
#define A4B_SZ (A4B_VL + 64*VS_STR*2)
#define A4_QS  (2*A4B_SZ)
#define A4_TOT (A4_QS + 128*QS_STR*2)

__global__ __launch_bounds__(256)
void attn4(const __nv_bfloat16* __restrict__ Qb, const __nv_bfloat16* __restrict__ Kb,
           const __nv_bfloat16* __restrict__ Vth, const __nv_bfloat16* __restrict__ Vtl,
           __nv_bfloat16* __restrict__ AOb) {
    extern __shared__ char smraw[];
    const uint32_t smB = smem_u32(smraw);
    __nv_bfloat16* Qs = (__nv_bfloat16*)(smraw + A4_QS);

    const int tid = threadIdx.x;
    const int wid = tid >> 5, lane = tid & 31;
    const int bid = blockIdx.x;
    const int qt = 15 - (bid >> 4);
    const int h = bid & 15;
    const int q0 = qt * 128;
    const int wm = wid * 16;

    const int a_row = (lane & 15);
    const int a_koff = (lane >> 4) * 8;
    const int b_row = (lane & 7) + ((lane & 16) >> 1);
    const int b_koff = ((lane >> 3) & 1) * 8;
    const int er = lane >> 2, ec = (lane & 3) * 2;

    const __nv_bfloat16* KbH = Kb + ((size_t)h * Lseq) * KQ3;
    const __nv_bfloat16* VhH = Vth + ((size_t)h * HD) * Lseq;
    const __nv_bfloat16* VlH = Vtl + ((size_t)h * HD) * Lseq;

    auto ld_tile = [&](int kt, int s) {
        const int k0 = kt * 64;
        const uint32_t stB = smB + (uint32_t)s * A4B_SZ;
        const __nv_bfloat16* ks = KbH + (size_t)k0 * KQ3;
        for (int i = tid; i < 64 * 30; i += 256) {
            int r = i / 30, c = i % 30;
            cp_async16(stB + ((uint32_t)(r * KS_STR + c * 8) << 1), ks + r * KQ3 + c * 8);
        }
        for (int i = tid; i < 64 * 8; i += 256) {
            int d = i >> 3, c = i & 7;
            uint32_t off = (uint32_t)(d * VS_STR + c * 8) << 1;
            const size_t go = (size_t)d * Lseq + k0 + c * 8;
            cp_async16(stB + A4B_VH + off, VhH + go);
            cp_async16(stB + A4B_VL + off, VlH + go);
        }
    };

    ld_tile(0, 0);
    CP_COMMIT();
    {
        const uint4* src = (const uint4*)(Qb + ((size_t)h * Lseq + q0) * KQ3);
        for (int i = tid; i < 128 * 30; i += 256) {
            int r = i / 30, c = i % 30;
            *(uint4*)&Qs[r * QS_STR + c * 8] = src[r * 30 + c];
        }
    }
    CP_WAIT0();
    __syncthreads();

    uint32_t qf[15][4];
    {
        const uint32_t qsB = smem_u32(Qs);
#pragma unroll
        for (int ks = 0; ks < 15; ks++)
            ldsm_x4(qf[ks][0], qf[ks][1], qf[ks][2], qf[ks][3],
                    qsB + ((wm + a_row) * QS_STR + ks * 16 + a_koff) * 2);
    }

    float m_run0 = NEG_BIG, m_run1 = NEG_BIG;
    float l_run0 = 0.f, l_run1 = 0.f;
    float acc_o[8][4];
#pragma unroll
    for (int d = 0; d < 8; d++)
#pragma unroll
        for (int c = 0; c < 4; c++) acc_o[d][c] = 0.f;

    const int nkt = 2 * qt + 2;
    for (int kt = 0; kt < nkt; kt++) {
        const int k0 = kt * 64;
        const int cur = kt & 1;
        if (kt + 1 < nkt) {
            ld_tile(kt + 1, cur ^ 1);
            CP_COMMIT();
        }
        const uint32_t stB = smB + (uint32_t)cur * A4B_SZ;
        const uint32_t ksB = stB;
        const uint32_t vhB = stB + A4B_VH;
        const uint32_t vlB = stB + A4B_VL;

        float s[8][4];
#pragma unroll
        for (int nt = 0; nt < 8; nt++)
#pragma unroll
            for (int c = 0; c < 4; c++) s[nt][c] = 0.f;
#pragma unroll
        for (int ks = 0; ks < 15; ks++) {
            const int kk = ks * 16;
            uint32_t bf[4][4];
#pragma unroll
            for (int nt2 = 0; nt2 < 4; nt2++)
                ldsm_x4(bf[nt2][0], bf[nt2][1], bf[nt2][2], bf[nt2][3],
                        ksB + ((nt2 * 16 + b_row) * KS_STR + kk + b_koff) * 2);
#pragma unroll
            for (int nt = 0; nt < 8; nt++)
                mma_bf16(s[nt], qf[ks][0], qf[ks][1], qf[ks][2], qf[ks][3],
                         bf[nt >> 1][(nt & 1) * 2], bf[nt >> 1][(nt & 1) * 2 + 1]);
        }

        if (kt >= 2 * qt) {
            const int r0 = q0 + wm + er, r1 = r0 + 8;
#pragma unroll
            for (int nt = 0; nt < 8; nt++) {
                const int c0 = k0 + nt * 8 + ec;
                if (c0     > r0) s[nt][0] = NEG_BIG;
                if (c0 + 1 > r0) s[nt][1] = NEG_BIG;
                if (c0     > r1) s[nt][2] = NEG_BIG;
                if (c0 + 1 > r1) s[nt][3] = NEG_BIG;
            }
        }

        float mx0 = s[0][0], mx1 = s[0][2];
#pragma unroll
        for (int nt = 0; nt < 8; nt++) {
            mx0 = fmaxf(mx0, fmaxf(s[nt][0], s[nt][1]));
            mx1 = fmaxf(mx1, fmaxf(s[nt][2], s[nt][3]));
        }
        mx0 = fmaxf(mx0, __shfl_xor_sync(0xffffffffu, mx0, 1));
        mx0 = fmaxf(mx0, __shfl_xor_sync(0xffffffffu, mx0, 2));
        mx1 = fmaxf(mx1, __shfl_xor_sync(0xffffffffu, mx1, 1));
        mx1 = fmaxf(mx1, __shfl_xor_sync(0xffffffffu, mx1, 2));
        float mnew0 = fmaxf(m_run0, mx0);
        float mnew1 = fmaxf(m_run1, mx1);
        float scale0 = __expf(m_run0 - mnew0);
        float scale1 = __expf(m_run1 - mnew1);

        float sum0 = 0.f, sum1 = 0.f;
#pragma unroll
        for (int nt = 0; nt < 8; nt++) {
            s[nt][0] = __expf(s[nt][0] - mnew0); sum0 += s[nt][0];
            s[nt][1] = __expf(s[nt][1] - mnew0); sum0 += s[nt][1];
            s[nt][2] = __expf(s[nt][2] - mnew1); sum1 += s[nt][2];
            s[nt][3] = __expf(s[nt][3] - mnew1); sum1 += s[nt][3];
        }
        sum0 += __shfl_xor_sync(0xffffffffu, sum0, 1);
        sum0 += __shfl_xor_sync(0xffffffffu, sum0, 2);
        sum1 += __shfl_xor_sync(0xffffffffu, sum1, 1);
        sum1 += __shfl_xor_sync(0xffffffffu, sum1, 2);
        m_run0 = mnew0; m_run1 = mnew1;
        l_run0 = l_run0 * scale0 + sum0;
        l_run1 = l_run1 * scale1 + sum1;

#pragma unroll
        for (int d = 0; d < 8; d++) {
            acc_o[d][0] *= scale0; acc_o[d][1] *= scale0;
            acc_o[d][2] *= scale1; acc_o[d][3] *= scale1;
        }

#pragma unroll
        for (int kk = 0; kk < 4; kk++) {
            float p00 = s[2*kk][0],   p01 = s[2*kk][1];
            float p02 = s[2*kk][2],   p03 = s[2*kk][3];
            float p10 = s[2*kk+1][0], p11 = s[2*kk+1][1];
            float p12 = s[2*kk+1][2], p13 = s[2*kk+1][3];
            uint32_t ah0 = pack_bf16x2(p00, p01);
            uint32_t ah1 = pack_bf16x2(p02, p03);
            uint32_t ah2 = pack_bf16x2(p10, p11);
            uint32_t ah3 = pack_bf16x2(p12, p13);
            __nv_bfloat162* hv;
            hv = (__nv_bfloat162*)&ah0;
            uint32_t al0 = pack_bf16x2(p00 - __bfloat162float(hv->x), p01 - __bfloat162float(hv->y));
            hv = (__nv_bfloat162*)&ah1;
            uint32_t al1 = pack_bf16x2(p02 - __bfloat162float(hv->x), p03 - __bfloat162float(hv->y));
            hv = (__nv_bfloat162*)&ah2;
            uint32_t al2 = pack_bf16x2(p10 - __bfloat162float(hv->x), p11 - __bfloat162float(hv->y));
            hv = (__nv_bfloat162*)&ah3;
            uint32_t al3 = pack_bf16x2(p12 - __bfloat162float(hv->x), p13 - __bfloat162float(hv->y));

            const int kko = kk * 16;
            uint32_t bh[4][4], bl[4][4];
#pragma unroll
            for (int dt2 = 0; dt2 < 4; dt2++) {
                ldsm_x4(bh[dt2][0], bh[dt2][1], bh[dt2][2], bh[dt2][3],
                        vhB + ((dt2 * 16 + b_row) * VS_STR + kko + b_koff) * 2);
                ldsm_x4(bl[dt2][0], bl[dt2][1], bl[dt2][2], bl[dt2][3],
                        vlB + ((dt2 * 16 + b_row) * VS_STR + kko + b_koff) * 2);
            }
#pragma unroll
            for (int dt = 0; dt < 8; dt++) {
                uint32_t b0h = bh[dt >> 1][(dt & 1) * 2], b1h = bh[dt >> 1][(dt & 1) * 2 + 1];
                uint32_t b0l = bl[dt >> 1][(dt & 1) * 2], b1l = bl[dt >> 1][(dt & 1) * 2 + 1];
                mma_bf16(acc_o[dt], ah0, ah1, ah2, ah3, b0h, b1h);
                mma_bf16(acc_o[dt], al0, al1, al2, al3, b0h, b1h);
                mma_bf16(acc_o[dt], ah0, ah1, ah2, ah3, b0l, b1l);
            }
        }
        CP_WAIT0();
        __syncthreads();
    }

    const float inv0 = 1.f / l_run0;
    const float inv1 = 1.f / l_run1;
    const int row0 = q0 + wm + er;
#pragma unroll
    for (int dt = 0; dt < 8; dt++) {
        const int col = h * HD + dt * 8 + ec;
        {
            float o0 = acc_o[dt][0] * inv0, o1 = acc_o[dt][1] * inv0;
            uint32_t hi = pack_bf16x2(o0, o1);
            __nv_bfloat162 h2 = *(__nv_bfloat162*)&hi;
            uint32_t lo = pack_bf16x2(o0 - __bfloat162float(h2.x),
                                      o1 - __bfloat162float(h2.y));
            *(uint32_t*)&AOb[(size_t)row0 * K2 + col] = hi;
            *(uint32_t*)&AOb[(size_t)row0 * K2 + 1024 + col] = lo;
        }
        {
            float o0 = acc_o[dt][2] * inv1, o1 = acc_o[dt][3] * inv1;
            uint32_t hi = pack_bf16x2(o0, o1);
            __nv_bfloat162 h2 = *(__nv_bfloat162*)&hi;
            uint32_t lo = pack_bf16x2(o0 - __bfloat162float(h2.x),
                                      o1 - __bfloat162float(h2.y));
            *(uint32_t*)&AOb[(size_t)(row0 + 8) * K2 + col] = hi;
            *(uint32_t*)&AOb[(size_t)(row0 + 8) * K2 + 1024 + col] = lo;
        }
    }
}

// ---------------------------------------------------------------------------
// Residual + LayerNorm with smem-cached row
// ---------------------------------------------------------------------------
__global__ __launch_bounds__(256)
void ln_kernel(const float* __restrict__ xr, const float* __restrict__ proj,
               const float* __restrict__ gamma, const float* __restrict__ beta,
               float* __restrict__ out) {
    const int row = blockIdx.x;
    const int tid = threadIdx.x;
    __shared__ float hrow[Dm];
    __shared__ float red[2][8];
    const float* a = xr + (long)row * Dm;
    const float* b = proj + (long)row * Dm;
    float s = 0.f, s2 = 0.f;
    for (int i = tid; i < Dm; i += 256) {
        float v = a[i] + b[i];
        hrow[i] = v;
        s += v; s2 += v * v;
    }
#pragma unroll
    for (int o = 16; o; o >>= 1) {
        s  += __shfl_xor_sync(0xffffffffu, s,  o);
        s2 += __shfl_xor_sync(0xffffffffu, s2, o);
    }
    if ((tid & 31) == 0) { red[0][tid >> 5] = s; red[1][tid >> 5] = s2; }
    __syncthreads();
    if (tid < 32) {
        s  = (tid < 8) ? red[0][tid] : 0.f;
        s2 = (tid < 8) ? red[1][tid] : 0.f;
#pragma unroll
        for (int o = 4; o; o >>= 1) {
            s  += __shfl_xor_sync(0xffffffffu, s,  o);
            s2 += __shfl_xor_sync(0xffffffffu, s2, o);
        }
        if (tid == 0) { red[0][0] = s; red[1][0] = s2; }
    }
    __syncthreads();
    float mu = red[0][0] * (1.f / Dm);
    float var = red[1][0] * (1.f / Dm) - mu * mu;
    float rstd = rsqrtf(var + 1e-5f);
    for (int i = tid; i < Dm; i += 256) {
        out[(long)row * Dm + i] = (hrow[i] - mu) * rstd * gamma[i] + beta[i];
    }
}

// ---------------------------------------------------------------------------
extern "C" void kernel_launch(void* const* d_in, const int* in_sizes, int n_in,
                              void* d_out, int out_size) {
    const float* x_real = (const float*)d_in[0];
    const float* x_imag = (const float*)d_in[1];
    const float* Wq     = (const float*)d_in[2];
    const float* Wk     = (const float*)d_in[3];
    const float* Wv     = (const float*)d_in[4];
    const float* Wqp    = (const float*)d_in[5];
    const float* bqp    = (const float*)d_in[6];
    const float* Wkp    = (const float*)d_in[7];
    const float* bkp    = (const float*)d_in[8];
    const float* Wo     = (const float*)d_in[9];
    const float* alogit = (const float*)d_in[10];
    const float* lng    = (const float*)d_in[11];
    const float* lnb    = (const float*)d_in[12];

    float *pQtKt, *pP2;
    __nv_bfloat16 *pAb, *pAib, *pAOb, *pBqkv, *pBp2, *pBo;
    __nv_bfloat16 *pQb, *pKb, *pVth, *pVtl;
    cudaGetSymbolAddress((void**)&pQtKt, g_QtKt);
    cudaGetSymbolAddress((void**)&pP2,   g_P2);
    cudaGetSymbolAddress((void**)&pAb,   g_Ab);
    cudaGetSymbolAddress((void**)&pAib,  g_Aib);
    cudaGetSymbolAddress((void**)&pAOb,  g_AOb);
    cudaGetSymbolAddress((void**)&pBqkv, g_Bqkv);
    cudaGetSymbolAddress((void**)&pBp2,  g_Bp2);
    cudaGetSymbolAddress((void**)&pBo,   g_Bo);
    cudaGetSymbolAddress((void**)&pQb,   g_Qb);
    cudaGetSymbolAddress((void**)&pKb,   g_Kb);
    cudaGetSymbolAddress((void**)&pVth,  g_Vth);
    cudaGetSymbolAddress((void**)&pVtl,  g_Vtl);

    cudaFuncSetAttribute(tgemm_fused, cudaFuncAttributeMaxDynamicSharedMemorySize, TG3_SMEM);
    cudaFuncSetAttribute(tgemm3, cudaFuncAttributeMaxDynamicSharedMemorySize, TG3_SMEM);
    cudaFuncSetAttribute(attn4, cudaFuncAttributeMaxDynamicSharedMemorySize, A4_TOT);

    // one-time inv_freq table
    init_invf<<<1, 64>>>();

    // batched activation + weight packs
    conv_a2b<<<dim3((Lseq * Dm) / 1024, 1, 2), 256>>>(x_real, x_imag, pAb, pAib);
    conv_b2b<<<dim3(Dm / 32, Dm / 32, 6), 256>>>(Wq, Wk, Wv, Wo, Wqp, Wkp,
                                                 pBqkv, pBo, pBp2);

    // fused QKV (384 CTAs) + phase (32 CTAs) GEMM launch
    tgemm_fused<<<416, 256, TG3_SMEM>>>(pAb, pBqkv, pAib, pBp2, pQtKt,
                                        alogit, pQb, pKb, pVth, pVtl);
    phase_pack<<<(Lseq * Pp) / 256, 256>>>(pQtKt, bqp, bkp, alogit, pQb, pKb);

    // attention, 1D load-balanced grid, fused [hi|lo] output pack
    attn4<<<256, 256, A4_TOT>>>(pQb, pKb, pVth, pVtl, pAOb);

    tgemm3<<<dim3(Dm / 128, Lseq / 128), 256, TG3_SMEM>>>(pAOb, pBo, pP2, Dm);
    ln_kernel<<<Lseq, 256>>>(x_real, pP2, lng, lnb, (float*)d_out);

    if (out_size >= 2 * Lseq * Dm) {
        cudaMemcpyAsync((float*)d_out + (long)Lseq * Dm, x_imag,
                        (size_t)Lseq * Dm * sizeof(float),
                        cudaMemcpyDeviceToDevice);
    }
}